// round 7
// baseline (speedup 1.0000x reference)
#include <cuda_runtime.h>
#include <cstdint>

// RandomPixelMapping: out[b,c,y,x] = table[b,c, clip(rint(x*255), 0, 255)]
// x: [64,3,512,512] f32, table: [64,3,256] f32, out: [64,3,512,512] f32.
// R7: conflict-free bank-replicated LUT + 256-bit global loads/stores
//     (ld/st.global.v8.b32, sm_10x) — 1KB per warp per instruction.

#define PLANE_ELEMS     (512 * 512)          // 262144 elems per (b,c) plane
#define VEC8_PER_PLANE  (PLANE_ELEMS / 8)    // 32768 float8 per plane
#define THREADS         256
#define CHUNKS          32                   // blocks per plane
#define VEC8_PER_BLOCK  (VEC8_PER_PLANE / CHUNKS)     // 1024 float8 per block
#define VEC8_PER_THREAD (VEC8_PER_BLOCK / THREADS)    // 4 float8 per thread

__device__ __forceinline__ void ld256(const float* p, uint32_t v[8]) {
    asm volatile("ld.global.v8.b32 {%0,%1,%2,%3,%4,%5,%6,%7}, [%8];"
                 : "=r"(v[0]), "=r"(v[1]), "=r"(v[2]), "=r"(v[3]),
                   "=r"(v[4]), "=r"(v[5]), "=r"(v[6]), "=r"(v[7])
                 : "l"(p));
}
__device__ __forceinline__ void st256(float* p, const uint32_t v[8]) {
    asm volatile("st.global.v8.b32 [%0], {%1,%2,%3,%4,%5,%6,%7,%8};"
                 :: "l"(p),
                    "r"(v[0]), "r"(v[1]), "r"(v[2]), "r"(v[3]),
                    "r"(v[4]), "r"(v[5]), "r"(v[6]), "r"(v[7])
                 : "memory");
}

__global__ __launch_bounds__(THREADS)
void RandomPixelMapping_19593640805006_kernel(
    const float* __restrict__ x,
    const float* __restrict__ table,
    float*       __restrict__ out)
{
    // Bank-replicated LUT: lane l always reads column l -> zero conflicts.
    __shared__ float lut[256][32];

    const int tid   = threadIdx.x;
    const int lane  = tid & 31;
    const int plane = blockIdx.y;                 // 0..191  (b*3 + c)

    // Vectorized rotated fill: warp STS.128 hits 8 distinct bank quads.
    {
        const float t = table[plane * 256 + tid];
        const float4 tv = make_float4(t, t, t, t);
        float4* row = reinterpret_cast<float4*>(lut[tid]);
#pragma unroll
        for (int j = 0; j < 8; ++j)
            row[(j + lane) & 7] = tv;
    }
    __syncthreads();

    // float index of this thread's first 8-wide chunk (32B aligned by construction)
    const size_t base = ((size_t)plane * VEC8_PER_PLANE
                       + (size_t)blockIdx.x * VEC8_PER_BLOCK
                       + tid) * 8;

    // Front-batch 4 independent 256-bit loads (same bytes-in-flight as 8x128b).
    uint32_t v[VEC8_PER_THREAD][8];
#pragma unroll
    for (int j = 0; j < VEC8_PER_THREAD; ++j)
        ld256(x + base + (size_t)j * (THREADS * 8), v[j]);

#pragma unroll
    for (int j = 0; j < VEC8_PER_THREAD; ++j) {
        uint32_t r[8];
#pragma unroll
        for (int e = 0; e < 8; ++e) {
            int idx = __float2int_rn(__uint_as_float(v[j][e]) * 255.0f);
            idx = min(max(idx, 0), 255);
            r[e] = __float_as_uint(lut[idx][lane]);
        }
        st256(out + base + (size_t)j * (THREADS * 8), r);
    }
}

extern "C" void kernel_launch(void* const* d_in, const int* in_sizes, int n_in,
                              void* d_out, int out_size)
{
    const float* x     = (const float*)d_in[0];
    const float* table = (const float*)d_in[1];
    float*       out   = (float*)d_out;

    dim3 grid(CHUNKS, 64 * 3);   // 32 chunks x 192 planes = 6144 CTAs
    RandomPixelMapping_19593640805006_kernel<<<grid, THREADS>>>(x, table, out);
}